// round 3
// baseline (speedup 1.0000x reference)
#include <cuda_runtime.h>
#include <cuda_bf16.h>
#include <math.h>
#include <stdint.h>

#define NB 8
#define LW 512
#define LE 64
#define SS 576
#define HH 1024
#define NHEAD 16
#define HD 64
#define MTOT (NB*SS)      // 4608
#define K3 (3*HH)         // 3072

// ---------------- scratch (device globals; no allocation) ----------------
__device__ float g_x  [ (long)MTOT * HH ];
__device__ float g_q  [ (long)MTOT * HH ];
__device__ float g_k  [ (long)MTOT * HH ];
__device__ float g_v  [ (long)MTOT * HH ];
__device__ float g_ctx[ (long)MTOT * HH ];
__device__ float g_y  [ (long)MTOT * HH ];
__device__ __nv_bfloat16 g_a [ (long)MTOT * K3 ];       // A' = [hi | hi | lo]
__device__ __nv_bfloat16 g_wb[ 4L * HH * K3 ];          // B' = [hiW^T | loW^T | hiW^T]

__device__ __forceinline__ uint32_t smem_u32(const void* p) {
    uint32_t a;
    asm("{ .reg .u64 t; cvta.to.shared.u64 t, %1; cvt.u32.u64 %0, t; }" : "=r"(a) : "l"(p));
    return a;
}

// ---------------- concat word/entity into g_x [B,S,H] ----------------
__global__ void concat_kernel(const float* __restrict__ w,
                              const float* __restrict__ e) {
    long i = (long)blockIdx.x * blockDim.x + threadIdx.x;
    long n4 = (long)MTOT * HH / 4;
    if (i >= n4) return;
    long idx = i * 4;
    int b = (int)(idx / ((long)SS * HH));
    long rem = idx % ((long)SS * HH);
    int s = (int)(rem / HH);
    int h = (int)(rem % HH);
    float4 val;
    if (s < LW) val = *(const float4*)&w[((long)b * LW + s) * HH + h];
    else        val = *(const float4*)&e[((long)b * LE + (s - LW)) * HH + h];
    *(float4*)&g_x[idx] = val;
}

// ---------------- A-side hi/lo bf16 split: X[M,1024] -> A'[M,3072] ----------
__global__ __launch_bounds__(256)
void conv_a_kernel(const float* __restrict__ X) {
    long i = (long)blockIdx.x * blockDim.x + threadIdx.x;  // float4 index
    long n4 = (long)MTOT * HH / 4;
    if (i >= n4) return;
    int m = (int)(i / 256);
    int k4 = (int)(i % 256) * 4;
    float4 x = *(const float4*)&X[(long)m * HH + k4];
    __nv_bfloat16 h0 = __float2bfloat16(x.x), h1 = __float2bfloat16(x.y);
    __nv_bfloat16 h2 = __float2bfloat16(x.z), h3 = __float2bfloat16(x.w);
    __nv_bfloat16 l0 = __float2bfloat16(x.x - __bfloat162float(h0));
    __nv_bfloat16 l1 = __float2bfloat16(x.y - __bfloat162float(h1));
    __nv_bfloat16 l2 = __float2bfloat16(x.z - __bfloat162float(h2));
    __nv_bfloat16 l3 = __float2bfloat16(x.w - __bfloat162float(h3));
    uint32_t hi01, hi23, lo01, lo23;
    { __nv_bfloat162 t = __nv_bfloat162(h0, h1); hi01 = *(uint32_t*)&t; }
    { __nv_bfloat162 t = __nv_bfloat162(h2, h3); hi23 = *(uint32_t*)&t; }
    { __nv_bfloat162 t = __nv_bfloat162(l0, l1); lo01 = *(uint32_t*)&t; }
    { __nv_bfloat162 t = __nv_bfloat162(l2, l3); lo23 = *(uint32_t*)&t; }
    uint2 hv = make_uint2(hi01, hi23);
    uint2 lv = make_uint2(lo01, lo23);
    __nv_bfloat16* base = g_a + (long)m * K3;
    *(uint2*)(base + k4)           = hv;
    *(uint2*)(base + HH + k4)      = hv;
    *(uint2*)(base + 2 * HH + k4)  = lv;
}

// -------- W transpose + hi/lo split: W[K,N] -> B'[N,3072] = [hiWt|loWt|hiWt] --
__global__ __launch_bounds__(256)
void conv_w_kernel(const float* __restrict__ W, __nv_bfloat16* __restrict__ out) {
    __shared__ float tile[32][33];
    int bn = blockIdx.x * 32;   // n
    int bk = blockIdx.y * 32;   // k
    int tid = threadIdx.x;
    int tx = tid % 32, ty = tid / 32;   // ty 0..7
    #pragma unroll
    for (int r = 0; r < 4; r++)
        tile[ty + r * 8][tx] = W[(long)(bk + ty + r * 8) * HH + bn + tx];
    __syncthreads();
    #pragma unroll
    for (int r = 0; r < 2; r++) {
        int e = tid + r * 256;           // 0..511
        int nl = e / 16;
        int kl = (e % 16) * 2;
        float a0 = tile[kl][nl], a1 = tile[kl + 1][nl];
        __nv_bfloat16 h0 = __float2bfloat16(a0), h1 = __float2bfloat16(a1);
        __nv_bfloat16 l0 = __float2bfloat16(a0 - __bfloat162float(h0));
        __nv_bfloat16 l1 = __float2bfloat16(a1 - __bfloat162float(h1));
        __nv_bfloat162 hp(h0, h1), lp(l0, l1);
        uint32_t hu = *(uint32_t*)&hp, lu = *(uint32_t*)&lp;
        __nv_bfloat16* row = out + (long)(bn + nl) * K3 + bk + kl;
        *(uint32_t*)(row)          = hu;
        *(uint32_t*)(row + HH)     = lu;
        *(uint32_t*)(row + 2 * HH) = hu;
    }
}

// ================ HMMA (mma.sync) bf16 GEMM =================
// C[M,1024] = A'[M,3072] x B'[1024,3072]^T  (+bias, +resid)
// CTA tile 128x128, BK=32, 8 warps of 32x64, cp.async double buffer.
#define BK 32
#define AST 40                 // padded smem row stride (elements)
#define NITER (K3 / BK)        // 96

__device__ __forceinline__ void ldmatrix_x4(uint32_t* r, uint32_t addr) {
    asm volatile("ldmatrix.sync.aligned.m8n8.x4.shared.b16 {%0,%1,%2,%3}, [%4];"
                 : "=r"(r[0]), "=r"(r[1]), "=r"(r[2]), "=r"(r[3]) : "r"(addr));
}
__device__ __forceinline__ void mma16816(float* d, const uint32_t* a,
                                         uint32_t b0, uint32_t b1) {
    asm volatile("mma.sync.aligned.m16n8k16.row.col.f32.bf16.bf16.f32 "
                 "{%0,%1,%2,%3},{%4,%5,%6,%7},{%8,%9},{%0,%1,%2,%3};"
                 : "+f"(d[0]), "+f"(d[1]), "+f"(d[2]), "+f"(d[3])
                 : "r"(a[0]), "r"(a[1]), "r"(a[2]), "r"(a[3]), "r"(b0), "r"(b1));
}
__device__ __forceinline__ void cp_async16(uint32_t dst, const void* src) {
    asm volatile("cp.async.cg.shared.global [%0], [%1], 16;" :: "r"(dst), "l"(src));
}
#define CP_COMMIT() asm volatile("cp.async.commit_group;" ::: "memory")
#define CP_WAIT1()  asm volatile("cp.async.wait_group 1;" ::: "memory")
#define CP_WAIT0()  asm volatile("cp.async.wait_group 0;" ::: "memory")

template<bool RESID>
__global__ __launch_bounds__(256)
void mma_gemm_kernel(const __nv_bfloat16* __restrict__ A,
                     const __nv_bfloat16* __restrict__ B,
                     const float* __restrict__ bias,
                     const float* __restrict__ resid,
                     float* __restrict__ C) {
    __shared__ __nv_bfloat16 sA[2][128 * AST];
    __shared__ __nv_bfloat16 sB[2][128 * AST];

    int tid = threadIdx.x;
    int lane = tid & 31, wid = tid >> 5;
    int bm = blockIdx.y * 128;
    int bn = blockIdx.x * 128;
    int wm = wid & 3, wn = wid >> 2;     // warp tile: rows wm*32, cols wn*64

    const __nv_bfloat16* Abase = A + (long)bm * K3;
    const __nv_bfloat16* Bbase = B + (long)bn * K3;

    // loader: each thread moves 2x16B for A and 2x16B for B per chunk
    int lrow = tid & 127;          // 0..127
    int lk   = tid >> 7;           // 0..1  -> k16 = lk, lk+2

    float acc[2][8][4];
    #pragma unroll
    for (int i = 0; i < 2; i++)
        #pragma unroll
        for (int j = 0; j < 8; j++)
            #pragma unroll
            for (int c = 0; c < 4; c++) acc[i][j][c] = 0.f;

    // precomputed smem write addrs (per buffer)
    uint32_t wA[2][2], wB[2][2];
    #pragma unroll
    for (int b = 0; b < 2; b++)
        #pragma unroll
        for (int p = 0; p < 2; p++) {
            int k16 = lk + p * 2;
            wA[b][p] = smem_u32(&sA[b][lrow * AST + k16 * 8]);
            wB[b][p] = smem_u32(&sB[b][lrow * AST + k16 * 8]);
        }

    auto load_chunk = [&](int i, int b) {
        long koff = (long)i * BK;
        #pragma unroll
        for (int p = 0; p < 2; p++) {
            int k16 = lk + p * 2;
            cp_async16(wA[b][p], Abase + (long)lrow * K3 + koff + k16 * 8);
            cp_async16(wB[b][p], Bbase + (long)lrow * K3 + koff + k16 * 8);
        }
    };

    load_chunk(0, 0); CP_COMMIT();
    load_chunk(1, 1); CP_COMMIT();

    // ldmatrix source addresses (depend on lane only)
    // A: lanes 0-7 rows r, k0 | 8-15 rows r+8, k0 | 16-23 rows r, k0+8 | 24-31 rows r+8, k0+8
    int a_r = (lane & 15);
    int a_c = (lane >> 4) << 3;
    // B: lanes 0-7 (n r, k0) | 8-15 (n r, k0+8) | 16-23 (n r+8, k0) | 24-31 (n r+8, k0+8)
    int b_r = (lane & 7) + ((lane >> 4) << 3);
    int b_c = ((lane >> 3) & 1) << 3;

    for (int i = 0; i < NITER; i++) {
        if (i == NITER - 1) { CP_WAIT0(); } else { CP_WAIT1(); }
        __syncthreads();
        int buf = i & 1;
        const __nv_bfloat16* pA = &sA[buf][(wm * 32) * AST];
        const __nv_bfloat16* pB = &sB[buf][(wn * 64) * AST];
        #pragma unroll
        for (int ks = 0; ks < 2; ks++) {
            int k0 = ks * 16;
            uint32_t a[2][4];
            #pragma unroll
            for (int mf = 0; mf < 2; mf++)
                ldmatrix_x4(a[mf], smem_u32(pA + (mf * 16 + a_r) * AST + k0 + a_c));
            uint32_t bfr[4][4];
            #pragma unroll
            for (int bi = 0; bi < 4; bi++)
                ldmatrix_x4(bfr[bi], smem_u32(pB + (bi * 16 + b_r) * AST + k0 + b_c));
            #pragma unroll
            for (int mf = 0; mf < 2; mf++)
                #pragma unroll
                for (int nf = 0; nf < 8; nf++) {
                    int bq = nf >> 1, off = (nf & 1) * 2;
                    mma16816(acc[mf][nf], a[mf], bfr[bq][off], bfr[bq][off + 1]);
                }
        }
        __syncthreads();
        if (i + 2 < NITER) { load_chunk(i + 2, buf); CP_COMMIT(); }
    }

    // epilogue
    int qrow = lane >> 2;          // 0..7
    int qcol = (lane & 3) * 2;     // 0,2,4,6
    #pragma unroll
    for (int mf = 0; mf < 2; mf++) {
        #pragma unroll
        for (int nf = 0; nf < 8; nf++) {
            int n = bn + wn * 64 + nf * 8 + qcol;
            float2 bi = *(const float2*)&bias[n];
            #pragma unroll
            for (int half = 0; half < 2; half++) {
                long m = bm + wm * 32 + mf * 16 + qrow + half * 8;
                float2 o;
                o.x = acc[mf][nf][half * 2 + 0] + bi.x;
                o.y = acc[mf][nf][half * 2 + 1] + bi.y;
                if (RESID) {
                    float2 rv = *(const float2*)&resid[m * HH + n];
                    o.x += rv.x; o.y += rv.y;
                }
                *(float2*)&C[m * HH + n] = o;
            }
        }
    }
}

// ---------------- attention: per (b, head, 8-query tile) -------------------
#define QT 8
#define NQT (SS / QT)     // 72
__global__ __launch_bounds__(256)
void attn_kernel(const float* __restrict__ mask) {
    int idx = blockIdx.x;
    int t = idx % NQT;  idx /= NQT;
    int h = idx % NHEAD;
    int b = idx / NHEAD;
    int q0 = t * QT;

    __shared__ float qs[QT][64];
    __shared__ float kts[64][68];
    __shared__ float sc[QT][SS];

    int tid = threadIdx.x;
    const float* qbase = g_q + (long)b * SS * HH + h * HD;
    const float* kbase = g_k + (long)b * SS * HH + h * HD;
    const float* vbase = g_v + (long)b * SS * HH + h * HD;

    if (tid < 128) {
        int r = tid / 16;
        int c = (tid % 16) * 4;
        *(float4*)&qs[r][c] = *(const float4*)&qbase[(long)(q0 + r) * HH + c];
    }
    __syncthreads();

    int qi = tid / 64;
    int kj = tid % 64;
    for (int kt = 0; kt < 9; kt++) {
        #pragma unroll
        for (int r4 = 0; r4 < 4; r4++) {
            int e = tid + r4 * 256;
            int row = e / 16;
            int col = (e % 16) * 4;
            *(float4*)&kts[row][col] =
                *(const float4*)&kbase[(long)(kt * 64 + row) * HH + col];
        }
        __syncthreads();
        float mk = mask[b * SS + kt * 64 + kj];
        #pragma unroll
        for (int qq = 0; qq < 2; qq++) {
            int q = qi + qq * 4;
            float s = 0.f;
            #pragma unroll
            for (int d4 = 0; d4 < 16; d4++) {
                float4 a = *(const float4*)&qs[q][d4 * 4];
                float4 kv = *(const float4*)&kts[kj][d4 * 4];
                s += a.x * kv.x + a.y * kv.y + a.z * kv.z + a.w * kv.w;
            }
            sc[q][kt * 64 + kj] = s * 0.125f + mk;
        }
        __syncthreads();
    }

    {
        int w = tid / 32, lane = tid % 32;
        if (w < QT) {
            int r = w;
            float m = -1e30f;
            for (int j = lane; j < SS; j += 32) m = fmaxf(m, sc[r][j]);
            #pragma unroll
            for (int o = 16; o > 0; o >>= 1)
                m = fmaxf(m, __shfl_xor_sync(0xffffffff, m, o));
            float sum = 0.f;
            for (int j = lane; j < SS; j += 32) {
                float p = __expf(sc[r][j] - m);
                sc[r][j] = p;
                sum += p;
            }
            #pragma unroll
            for (int o = 16; o > 0; o >>= 1)
                sum += __shfl_xor_sync(0xffffffff, sum, o);
            float inv = 1.0f / sum;
            for (int j = lane; j < SS; j += 32) sc[r][j] *= inv;
        }
    }
    __syncthreads();

    {
        int d = tid % 64;
        int qg = tid / 64;
        float a00 = 0.f, a01 = 0.f, a10 = 0.f, a11 = 0.f;
        const float* vp = vbase + d;
        #pragma unroll 4
        for (int j = 0; j < SS; j += 2) {
            float v0 = vp[(long)j * HH];
            float v1 = vp[(long)(j + 1) * HH];
            a00 += sc[qg][j] * v0;       a01 += sc[qg][j + 1] * v1;
            a10 += sc[qg + 4][j] * v0;   a11 += sc[qg + 4][j + 1] * v1;
        }
        float* ctxbase = g_ctx + ((long)b * SS + q0) * HH + h * HD;
        ctxbase[(long)qg * HH + d] = a00 + a01;
        ctxbase[(long)(qg + 4) * HH + d] = a10 + a11;
    }
}

// ---------------- LayerNorm + output split ordering ----------------
__global__ __launch_bounds__(256)
void ln_out_kernel(const float* __restrict__ ln_w, const float* __restrict__ ln_b,
                   float* __restrict__ out) {
    int row = blockIdx.x;
    int b = row / SS, s = row % SS;
    const float* y = g_y + (long)row * HH;
    int tid = threadIdx.x;

    float4 v = *(const float4*)&y[tid * 4];
    float sum = v.x + v.y + v.z + v.w;
    float sq  = v.x * v.x + v.y * v.y + v.z * v.z + v.w * v.w;

    __shared__ float s_sum[8], s_sq[8], s_stats[2];
    int w = tid / 32, lane = tid % 32;
    #pragma unroll
    for (int o = 16; o > 0; o >>= 1) {
        sum += __shfl_xor_sync(0xffffffff, sum, o);
        sq  += __shfl_xor_sync(0xffffffff, sq,  o);
    }
    if (lane == 0) { s_sum[w] = sum; s_sq[w] = sq; }
    __syncthreads();
    if (tid == 0) {
        float ts = 0.f, tq = 0.f;
        #pragma unroll
        for (int i = 0; i < 8; i++) { ts += s_sum[i]; tq += s_sq[i]; }
        float mean = ts * (1.0f / HH);
        float var  = tq * (1.0f / HH) - mean * mean;
        s_stats[0] = mean;
        s_stats[1] = rsqrtf(var + 1e-12f);
    }
    __syncthreads();
    float mean = s_stats[0], inv = s_stats[1];

    long dst;
    if (s < LW) dst = ((long)b * LW + s) * HH;
    else        dst = (long)NB * LW * HH + ((long)b * LE + (s - LW)) * HH;

    float4 w4 = *(const float4*)&ln_w[tid * 4];
    float4 b4 = *(const float4*)&ln_b[tid * 4];
    float4 o;
    o.x = (v.x - mean) * inv * w4.x + b4.x;
    o.y = (v.y - mean) * inv * w4.y + b4.y;
    o.z = (v.z - mean) * inv * w4.z + b4.z;
    o.w = (v.w - mean) * inv * w4.w + b4.w;
    *(float4*)&out[dst + tid * 4] = o;
}

// ---------------- launch ----------------
extern "C" void kernel_launch(void* const* d_in, const int* in_sizes, int n_in,
                              void* d_out, int out_size) {
    const float* word = (const float*)d_in[0];
    const float* ent  = (const float*)d_in[1];
    const float* mask = (const float*)d_in[2];
    const float* Wq   = (const float*)d_in[3];
    const float* bq   = (const float*)d_in[4];
    const float* Wk   = (const float*)d_in[5];
    const float* bk   = (const float*)d_in[6];
    const float* Wv   = (const float*)d_in[7];
    const float* bv   = (const float*)d_in[8];
    const float* Wo   = (const float*)d_in[9];
    const float* bo   = (const float*)d_in[10];
    const float* lnw  = (const float*)d_in[11];
    const float* lnb  = (const float*)d_in[12];
    float* out = (float*)d_out;

    float *px, *pq, *pk, *pv, *pc, *py;
    __nv_bfloat16 *pa, *pwb;
    cudaGetSymbolAddress((void**)&px, g_x);
    cudaGetSymbolAddress((void**)&pq, g_q);
    cudaGetSymbolAddress((void**)&pk, g_k);
    cudaGetSymbolAddress((void**)&pv, g_v);
    cudaGetSymbolAddress((void**)&pc, g_ctx);
    cudaGetSymbolAddress((void**)&py, g_y);
    cudaGetSymbolAddress((void**)&pa, g_a);
    cudaGetSymbolAddress((void**)&pwb, g_wb);

    long n4 = (long)MTOT * HH / 4;
    int cblocks = (int)((n4 + 255) / 256);

    // 1) concat
    concat_kernel<<<cblocks, 256>>>(word, ent);

    // 2) convert A (x) and all four weights to bf16 hi/lo form
    conv_a_kernel<<<cblocks, 256>>>(px);
    {
        dim3 g(32, 32);
        conv_w_kernel<<<g, 256>>>(Wq, pwb + 0L * HH * K3);
        conv_w_kernel<<<g, 256>>>(Wk, pwb + 1L * HH * K3);
        conv_w_kernel<<<g, 256>>>(Wv, pwb + 2L * HH * K3);
        conv_w_kernel<<<g, 256>>>(Wo, pwb + 3L * HH * K3);
    }

    // 3) Q/K/V projections on tensor cores (mma.sync bf16, 3-term split)
    {
        dim3 grid(HH / 128, MTOT / 128);
        mma_gemm_kernel<false><<<grid, 256>>>(pa, pwb + 0L * HH * K3, bq, nullptr, pq);
        mma_gemm_kernel<false><<<grid, 256>>>(pa, pwb + 1L * HH * K3, bk, nullptr, pk);
        mma_gemm_kernel<false><<<grid, 256>>>(pa, pwb + 2L * HH * K3, bv, nullptr, pv);
    }

    // 4) attention
    attn_kernel<<<NB * NHEAD * NQT, 256>>>(mask);

    // 5) output projection (+bias+residual)
    conv_a_kernel<<<cblocks, 256>>>(pc);
    {
        dim3 grid(HH / 128, MTOT / 128);
        mma_gemm_kernel<true><<<grid, 256>>>(pa, pwb + 3L * HH * K3, bo, px, py);
    }

    // 6) LayerNorm + split write
    ln_out_kernel<<<MTOT, 256>>>(lnw, lnb, out);
}

// round 4
// speedup vs baseline: 1.5387x; 1.5387x over previous
#include <cuda_runtime.h>
#include <math.h>
#include <stdint.h>

#define NB 8
#define LW 512
#define LE 64
#define SS 576
#define HH 1024
#define NHEAD 16
#define HD 64
#define MTOT (NB*SS)      // 4608

// ---------------- scratch (device globals; no allocation) ----------------
__device__ float g_x  [ (long)MTOT * HH ];
__device__ float g_q  [ (long)MTOT * HH ];
__device__ float g_k  [ (long)MTOT * HH ];
__device__ float g_v  [ (long)MTOT * HH ];
__device__ float g_ctx[ (long)MTOT * HH ];
__device__ float g_y  [ (long)MTOT * HH ];

// ---------------- fast exp on the FMA pipe (no MUFU) ----------------
// exp(x) = 2^(x*log2e); n = rint(t), f in [-0.5,0.5], deg-5 Taylor, err < 3e-6
__device__ __forceinline__ float fexp(float x) {
    float t = x * 1.4426950408889634f;
    t = fmaxf(t, -120.0f);
    int   e = __float2int_rn(t);
    float f = t - (float)e;
    const float c1 = 0.6931471805599453f;
    const float c2 = 0.2402265069591007f;
    const float c3 = 0.0555041086648216f;
    const float c4 = 0.0096181291076285f;
    const float c5 = 0.0013333558146428f;
    float p = fmaf(f, c5, c4);
    p = fmaf(f, p, c3);
    p = fmaf(f, p, c2);
    p = fmaf(f, p, c1);
    p = fmaf(f, p, 1.0f);
    float sc = __int_as_float((e + 127) << 23);
    return sc * p;
}

__device__ __forceinline__ uint32_t smem_u32(const void* p) {
    uint32_t a;
    asm("{ .reg .u64 t; cvta.to.shared.u64 t, %1; cvt.u32.u64 %0, t; }" : "=r"(a) : "l"(p));
    return a;
}
__device__ __forceinline__ void cp_async16(uint32_t dst, const void* src) {
    asm volatile("cp.async.cg.shared.global [%0], [%1], 16;" :: "r"(dst), "l"(src));
}
#define CP_COMMIT() asm volatile("cp.async.commit_group;" ::: "memory")
#define CP_WAIT1()  asm volatile("cp.async.wait_group 1;" ::: "memory")
#define CP_WAIT0()  asm volatile("cp.async.wait_group 0;" ::: "memory")

// ---------------- concat word/entity into g_x [B,S,H] ----------------
__global__ void concat_kernel(const float* __restrict__ w,
                              const float* __restrict__ e) {
    long i = (long)blockIdx.x * blockDim.x + threadIdx.x;
    long n4 = (long)MTOT * HH / 4;
    if (i >= n4) return;
    long idx = i * 4;
    int b = (int)(idx / ((long)SS * HH));
    long rem = idx % ((long)SS * HH);
    int s = (int)(rem / HH);
    int h = (int)(rem % HH);
    float4 val;
    if (s < LW) val = *(const float4*)&w[((long)b * LW + s) * HH + h];
    else        val = *(const float4*)&e[((long)b * LE + (s - LW)) * HH + h];
    *(float4*)&g_x[idx] = val;
}

// ---------------- fp32 tiled GEMM (R1, proven): C = A*W + bias (+resid) ------
template<bool RESID>
__global__ __launch_bounds__(256)
void gemm_kernel(const float* __restrict__ A, const float* __restrict__ W,
                 const float* __restrict__ bias, const float* __restrict__ resid,
                 float* __restrict__ C, int M, int N, int K) {
    __shared__ float As[16][132];
    __shared__ float Bs[16][128];

    int tid = threadIdx.x;
    int bm = blockIdx.y * 128;
    int bn = blockIdx.x * 128;
    int ty = tid / 16, tx = tid % 16;

    float acc[8][8];
    #pragma unroll
    for (int i = 0; i < 8; i++)
        #pragma unroll
        for (int j = 0; j < 8; j++) acc[i][j] = 0.f;

    int arow = tid / 4;
    int acol = (tid % 4) * 4;
    int brow = tid / 32;
    int bcol = (tid % 32) * 4;

    for (int k0 = 0; k0 < K; k0 += 16) {
        #pragma unroll
        for (int r = 0; r < 2; r++) {
            int row = arow + r * 64;
            float4 a = *(const float4*)&A[(long)(bm + row) * K + k0 + acol];
            As[acol + 0][row] = a.x;
            As[acol + 1][row] = a.y;
            As[acol + 2][row] = a.z;
            As[acol + 3][row] = a.w;
        }
        #pragma unroll
        for (int r = 0; r < 2; r++) {
            int row = brow + r * 8;
            *(float4*)&Bs[row][bcol] =
                *(const float4*)&W[(long)(k0 + row) * N + bn + bcol];
        }
        __syncthreads();
        #pragma unroll
        for (int kk = 0; kk < 16; kk++) {
            float a[8], b[8];
            *(float4*)&a[0] = *(float4*)&As[kk][ty * 8];
            *(float4*)&a[4] = *(float4*)&As[kk][ty * 8 + 4];
            *(float4*)&b[0] = *(float4*)&Bs[kk][tx * 8];
            *(float4*)&b[4] = *(float4*)&Bs[kk][tx * 8 + 4];
            #pragma unroll
            for (int i = 0; i < 8; i++)
                #pragma unroll
                for (int j = 0; j < 8; j++)
                    acc[i][j] += a[i] * b[j];
        }
        __syncthreads();
    }

    #pragma unroll
    for (int i = 0; i < 8; i++) {
        long m = bm + ty * 8 + i;
        #pragma unroll
        for (int j = 0; j < 8; j += 4) {
            int n = bn + tx * 8 + j;
            float4 bi = *(const float4*)&bias[n];
            float4 o;
            o.x = acc[i][j + 0] + bi.x;
            o.y = acc[i][j + 1] + bi.y;
            o.z = acc[i][j + 2] + bi.z;
            o.w = acc[i][j + 3] + bi.w;
            if (RESID) {
                float4 r = *(const float4*)&resid[m * N + n];
                o.x += r.x; o.y += r.y; o.z += r.z; o.w += r.w;
            }
            *(float4*)&C[m * N + n] = o;
        }
    }
}

// ================= flash-style attention =================
// grid = NB * NHEAD * 9 blocks; block = 256 threads.
// 64 queries/block; 9 key chunks of 64; online softmax; poly exp.
// smem: qs[64][68] + ks[2][64][68] + vs[2][64][68] + pst[64][68] + ms[576]
#define NCHK (SS / 64)   // 9
#define ATT_SMEM ((64*68 + 2*64*68 + 2*64*68 + 64*68 + SS) * 4)

__global__ __launch_bounds__(256)
void flash_attn_kernel(const float* __restrict__ mask) {
    extern __shared__ float sm[];
    float (*qs)[68]  = (float(*)[68])sm;          // [64][68]
    float (*ks)[68]  = qs + 64;                   // [2*64][68]
    float (*vs)[68]  = ks + 128;                  // [2*64][68]
    float (*pst)[68] = vs + 128;                  // [64][68] : pst[j][q]
    float* msm       = (float*)(pst + 64);        // [576]

    int idx = blockIdx.x;
    int qt = idx % NCHK;  idx /= NCHK;
    int h  = idx % NHEAD;
    int b  = idx / NHEAD;
    int q0 = qt * 64;

    int tid = threadIdx.x;
    int qg = tid >> 4;          // 0..15 : q rows 4*qg .. +3
    int jg = tid & 15;          // 0..15 : j cols {jg+16*ij} / d4 = jg in phase 5

    const float* qb = g_q + (long)b * SS * HH + h * HD;
    const float* kb = g_k + (long)b * SS * HH + h * HD;
    const float* vb = g_v + (long)b * SS * HH + h * HD;

    // mask to smem
    for (int i = tid; i < SS; i += 256) msm[i] = mask[b * SS + i];
    // Q tile (plain loads)
    #pragma unroll
    for (int t = 0; t < 4; t++) {
        int e = tid + t * 256;
        int r = e >> 4, c = e & 15;
        *(float4*)&qs[r][c * 4] = *(const float4*)&qb[(long)(q0 + r) * HH + c * 4];
    }

    // prefetch chunk 0 into buf 0
    #pragma unroll
    for (int t = 0; t < 4; t++) {
        int e = tid + t * 256;
        int r = e >> 4, c = e & 15;
        cp_async16(smem_u32(&ks[r][c * 4]), kb + (long)r * HH + c * 4);
        cp_async16(smem_u32(&vs[r][c * 4]), vb + (long)r * HH + c * 4);
    }
    CP_COMMIT();

    float m[4], l[4];
    float4 acc4[4];
    #pragma unroll
    for (int i = 0; i < 4; i++) {
        m[i] = -1e30f; l[i] = 0.f;
        acc4[i] = make_float4(0.f, 0.f, 0.f, 0.f);
    }

    for (int c = 0; c < NCHK; c++) {
        int buf = c & 1;
        if (c + 1 < NCHK) {
            int nb_ = buf ^ 1;
            long rbase = (long)(c + 1) * 64;
            #pragma unroll
            for (int t = 0; t < 4; t++) {
                int e = tid + t * 256;
                int r = e >> 4, cc = e & 15;
                cp_async16(smem_u32(&ks[nb_ * 64 + r][cc * 4]),
                           kb + (rbase + r) * HH + cc * 4);
                cp_async16(smem_u32(&vs[nb_ * 64 + r][cc * 4]),
                           vb + (rbase + r) * HH + cc * 4);
            }
            CP_COMMIT();
            CP_WAIT1();
        } else {
            CP_WAIT0();
        }
        __syncthreads();

        // ---- phase 2: scores s[iq][ij], q = 4*qg+iq, j = jg + 16*ij ----
        float s[4][4];
        #pragma unroll
        for (int i = 0; i < 4; i++)
            #pragma unroll
            for (int j = 0; j < 4; j++) s[i][j] = 0.f;

        #pragma unroll
        for (int d4 = 0; d4 < 16; d4++) {
            float4 qv[4];
            #pragma unroll
            for (int iq = 0; iq < 4; iq++)
                qv[iq] = *(float4*)&qs[4 * qg + iq][d4 * 4];
            #pragma unroll
            for (int ij = 0; ij < 4; ij++) {
                float4 kv = *(float4*)&ks[buf * 64 + jg + 16 * ij][d4 * 4];
                #pragma unroll
                for (int iq = 0; iq < 4; iq++) {
                    s[iq][ij] = fmaf(qv[iq].x, kv.x, s[iq][ij]);
                    s[iq][ij] = fmaf(qv[iq].y, kv.y, s[iq][ij]);
                    s[iq][ij] = fmaf(qv[iq].z, kv.z, s[iq][ij]);
                    s[iq][ij] = fmaf(qv[iq].w, kv.w, s[iq][ij]);
                }
            }
        }

        // ---- phase 3/4: online softmax update ----
        float alpha[4];
        #pragma unroll
        for (int iq = 0; iq < 4; iq++) {
            float cm = -1e30f;
            #pragma unroll
            for (int ij = 0; ij < 4; ij++) {
                float v = s[iq][ij] * 0.125f + msm[c * 64 + jg + 16 * ij];
                s[iq][ij] = v;
                cm = fmaxf(cm, v);
            }
            #pragma unroll
            for (int o = 1; o < 16; o <<= 1)
                cm = fmaxf(cm, __shfl_xor_sync(0xffffffff, cm, o));
            float nm = fmaxf(m[iq], cm);
            alpha[iq] = fexp(m[iq] - nm);
            m[iq] = nm;
            float psum = 0.f;
            #pragma unroll
            for (int ij = 0; ij < 4; ij++) {
                float p = fexp(s[iq][ij] - nm);
                s[iq][ij] = p;
                psum += p;
            }
            #pragma unroll
            for (int o = 1; o < 16; o <<= 1)
                psum += __shfl_xor_sync(0xffffffff, psum, o);
            l[iq] = l[iq] * alpha[iq] + psum;
        }

        // write transposed probs: pst[j][4*qg .. +3]
        #pragma unroll
        for (int ij = 0; ij < 4; ij++) {
            float4 pv = make_float4(s[0][ij], s[1][ij], s[2][ij], s[3][ij]);
            *(float4*)&pst[jg + 16 * ij][4 * qg] = pv;
        }
        __syncthreads();

        // ---- phase 5: ctx accumulation; thread = (qg, d4=jg) ----
        #pragma unroll
        for (int iq = 0; iq < 4; iq++) {
            acc4[iq].x *= alpha[iq]; acc4[iq].y *= alpha[iq];
            acc4[iq].z *= alpha[iq]; acc4[iq].w *= alpha[iq];
        }
        #pragma unroll 4
        for (int j = 0; j < 64; j++) {
            float4 pv = *(float4*)&pst[j][4 * qg];
            float4 vv = *(float4*)&vs[buf * 64 + j][jg * 4];
            acc4[0].x = fmaf(pv.x, vv.x, acc4[0].x);
            acc4[0].y = fmaf(pv.x, vv.y, acc4[0].y);
            acc4[0].z = fmaf(pv.x, vv.z, acc4[0].z);
            acc4[0].w = fmaf(pv.x, vv.w, acc4[0].w);
            acc4[1].x = fmaf(pv.y, vv.x, acc4[1].x);
            acc4[1].y = fmaf(pv.y, vv.y, acc4[1].y);
            acc4[1].z = fmaf(pv.y, vv.z, acc4[1].z);
            acc4[1].w = fmaf(pv.y, vv.w, acc4[1].w);
            acc4[2].x = fmaf(pv.z, vv.x, acc4[2].x);
            acc4[2].y = fmaf(pv.z, vv.y, acc4[2].y);
            acc4[2].z = fmaf(pv.z, vv.z, acc4[2].z);
            acc4[2].w = fmaf(pv.z, vv.w, acc4[2].w);
            acc4[3].x = fmaf(pv.w, vv.x, acc4[3].x);
            acc4[3].y = fmaf(pv.w, vv.y, acc4[3].y);
            acc4[3].z = fmaf(pv.w, vv.z, acc4[3].z);
            acc4[3].w = fmaf(pv.w, vv.w, acc4[3].w);
        }
        __syncthreads();
    }

    // ---- output ----
    #pragma unroll
    for (int iq = 0; iq < 4; iq++) {
        float inv = 1.0f / l[iq];
        float4 o;
        o.x = acc4[iq].x * inv; o.y = acc4[iq].y * inv;
        o.z = acc4[iq].z * inv; o.w = acc4[iq].w * inv;
        long row = (long)b * SS + q0 + 4 * qg + iq;
        *(float4*)&g_ctx[row * HH + h * HD + jg * 4] = o;
    }
}

// ---------------- LayerNorm + output split ordering ----------------
__global__ __launch_bounds__(256)
void ln_out_kernel(const float* __restrict__ ln_w, const float* __restrict__ ln_b,
                   float* __restrict__ out) {
    int row = blockIdx.x;
    int b = row / SS, s = row % SS;
    const float* y = g_y + (long)row * HH;
    int tid = threadIdx.x;

    float4 v = *(const float4*)&y[tid * 4];
    float sum = v.x + v.y + v.z + v.w;
    float sq  = v.x * v.x + v.y * v.y + v.z * v.z + v.w * v.w;

    __shared__ float s_sum[8], s_sq[8], s_stats[2];
    int w = tid / 32, lane = tid % 32;
    #pragma unroll
    for (int o = 16; o > 0; o >>= 1) {
        sum += __shfl_xor_sync(0xffffffff, sum, o);
        sq  += __shfl_xor_sync(0xffffffff, sq,  o);
    }
    if (lane == 0) { s_sum[w] = sum; s_sq[w] = sq; }
    __syncthreads();
    if (tid == 0) {
        float ts = 0.f, tq = 0.f;
        #pragma unroll
        for (int i = 0; i < 8; i++) { ts += s_sum[i]; tq += s_sq[i]; }
        float mean = ts * (1.0f / HH);
        float var  = tq * (1.0f / HH) - mean * mean;
        s_stats[0] = mean;
        s_stats[1] = rsqrtf(var + 1e-12f);
    }
    __syncthreads();
    float mean = s_stats[0], inv = s_stats[1];

    long dst;
    if (s < LW) dst = ((long)b * LW + s) * HH;
    else        dst = (long)NB * LW * HH + ((long)b * LE + (s - LW)) * HH;

    float4 w4 = *(const float4*)&ln_w[tid * 4];
    float4 b4 = *(const float4*)&ln_b[tid * 4];
    float4 o;
    o.x = (v.x - mean) * inv * w4.x + b4.x;
    o.y = (v.y - mean) * inv * w4.y + b4.y;
    o.z = (v.z - mean) * inv * w4.z + b4.z;
    o.w = (v.w - mean) * inv * w4.w + b4.w;
    *(float4*)&out[dst + tid * 4] = o;
}

// ---------------- launch ----------------
extern "C" void kernel_launch(void* const* d_in, const int* in_sizes, int n_in,
                              void* d_out, int out_size) {
    const float* word = (const float*)d_in[0];
    const float* ent  = (const float*)d_in[1];
    const float* mask = (const float*)d_in[2];
    const float* Wq   = (const float*)d_in[3];
    const float* bq   = (const float*)d_in[4];
    const float* Wk   = (const float*)d_in[5];
    const float* bk   = (const float*)d_in[6];
    const float* Wv   = (const float*)d_in[7];
    const float* bv   = (const float*)d_in[8];
    const float* Wo   = (const float*)d_in[9];
    const float* bo   = (const float*)d_in[10];
    const float* lnw  = (const float*)d_in[11];
    const float* lnb  = (const float*)d_in[12];
    float* out = (float*)d_out;

    float *px, *pq, *pk, *pv, *pc, *py;
    cudaGetSymbolAddress((void**)&px, g_x);
    cudaGetSymbolAddress((void**)&pq, g_q);
    cudaGetSymbolAddress((void**)&pk, g_k);
    cudaGetSymbolAddress((void**)&pv, g_v);
    cudaGetSymbolAddress((void**)&pc, g_ctx);
    cudaGetSymbolAddress((void**)&py, g_y);

    cudaFuncSetAttribute(flash_attn_kernel,
                         cudaFuncAttributeMaxDynamicSharedMemorySize, ATT_SMEM);

    // 1) concat
    {
        long n4 = (long)MTOT * HH / 4;
        int blocks = (int)((n4 + 255) / 256);
        concat_kernel<<<blocks, 256>>>(word, ent);
    }

    // 2) Q/K/V projections (fp32 FFMA GEMM)
    {
        dim3 grid(HH / 128, MTOT / 128);
        gemm_kernel<false><<<grid, 256>>>(px, Wq, bq, nullptr, pq, MTOT, HH, HH);
        gemm_kernel<false><<<grid, 256>>>(px, Wk, bk, nullptr, pk, MTOT, HH, HH);
        gemm_kernel<false><<<grid, 256>>>(px, Wv, bv, nullptr, pv, MTOT, HH, HH);
    }

    // 3) flash attention
    flash_attn_kernel<<<NB * NHEAD * NCHK, 256, ATT_SMEM>>>(mask);

    // 4) output projection + bias + residual
    {
        dim3 grid(HH / 128, MTOT / 128);
        gemm_kernel<true><<<grid, 256>>>(pc, Wo, bo, px, py, MTOT, HH, HH);
    }

    // 5) LayerNorm + split write
    ln_out_kernel<<<MTOT, 256>>>(lnw, lnb, out);
}

// round 5
// speedup vs baseline: 1.5557x; 1.0110x over previous
#include <cuda_runtime.h>
#include <math.h>
#include <stdint.h>

#define NB 8
#define LW 512
#define LE 64
#define SS 576
#define HH 1024
#define NHEAD 16
#define HD 64
#define MTOT (NB*SS)      // 4608

typedef unsigned long long u64;

// ---------------- scratch (device globals; no allocation) ----------------
__device__ float g_x  [ (long)MTOT * HH ];
__device__ float g_q  [ (long)MTOT * HH ];
__device__ float g_k  [ (long)MTOT * HH ];
__device__ float g_v  [ (long)MTOT * HH ];
__device__ float g_ctx[ (long)MTOT * HH ];
__device__ float g_y  [ (long)MTOT * HH ];

// ---------------- packed f32x2 helpers ----------------
__device__ __forceinline__ u64 pack2(float lo, float hi) {
    u64 r; asm("mov.b64 %0, {%1, %2};" : "=l"(r) : "f"(lo), "f"(hi)); return r;
}
__device__ __forceinline__ void fma2(u64& d, u64 a, u64 b) {
    asm("fma.rn.f32x2 %0, %1, %2, %0;" : "+l"(d) : "l"(a), "l"(b));
}
__device__ __forceinline__ void mul2(u64& d, u64 a) {
    asm("mul.rn.f32x2 %0, %0, %1;" : "+l"(d) : "l"(a));
}

// ---------------- fast exp on the FMA pipe (no MUFU) ----------------
__device__ __forceinline__ float fexp(float x) {
    float t = x * 1.4426950408889634f;
    t = fmaxf(t, -120.0f);
    int   e = __float2int_rn(t);
    float f = t - (float)e;
    const float c1 = 0.6931471805599453f;
    const float c2 = 0.2402265069591007f;
    const float c3 = 0.0555041086648216f;
    const float c4 = 0.0096181291076285f;
    const float c5 = 0.0013333558146428f;
    float p = fmaf(f, c5, c4);
    p = fmaf(f, p, c3);
    p = fmaf(f, p, c2);
    p = fmaf(f, p, c1);
    p = fmaf(f, p, 1.0f);
    float sc = __int_as_float((e + 127) << 23);
    return sc * p;
}

__device__ __forceinline__ uint32_t smem_u32(const void* p) {
    uint32_t a;
    asm("{ .reg .u64 t; cvta.to.shared.u64 t, %1; cvt.u32.u64 %0, t; }" : "=r"(a) : "l"(p));
    return a;
}
__device__ __forceinline__ void cp_async16(uint32_t dst, const void* src) {
    asm volatile("cp.async.cg.shared.global [%0], [%1], 16;" :: "r"(dst), "l"(src));
}
#define CP_COMMIT() asm volatile("cp.async.commit_group;" ::: "memory")
#define CP_WAIT1()  asm volatile("cp.async.wait_group 1;" ::: "memory")
#define CP_WAIT0()  asm volatile("cp.async.wait_group 0;" ::: "memory")

// ---------------- concat word/entity into g_x [B,S,H] ----------------
__global__ void concat_kernel(const float* __restrict__ w,
                              const float* __restrict__ e) {
    long i = (long)blockIdx.x * blockDim.x + threadIdx.x;
    long n4 = (long)MTOT * HH / 4;
    if (i >= n4) return;
    long idx = i * 4;
    int b = (int)(idx / ((long)SS * HH));
    long rem = idx % ((long)SS * HH);
    int s = (int)(rem / HH);
    int h = (int)(rem % HH);
    float4 val;
    if (s < LW) val = *(const float4*)&w[((long)b * LW + s) * HH + h];
    else        val = *(const float4*)&e[((long)b * LE + (s - LW)) * HH + h];
    *(float4*)&g_x[idx] = val;
}

// ---------------- fp32 tiled GEMM with packed FFMA2 ----------
// BM=BN=128, BK=16, 256 threads, 8x8 microtile per thread (acc as 8x4 f32x2)
template<bool RESID>
__global__ __launch_bounds__(256)
void gemm_kernel(const float* __restrict__ A, const float* __restrict__ W,
                 const float* __restrict__ bias, const float* __restrict__ resid,
                 float* __restrict__ C, int M, int N, int K) {
    __shared__ float As[16][132];
    __shared__ float Bs[16][128];

    int tid = threadIdx.x;
    int bm = blockIdx.y * 128;
    int bn = blockIdx.x * 128;
    int ty = tid / 16, tx = tid % 16;

    u64 acc2[8][4];
    #pragma unroll
    for (int i = 0; i < 8; i++)
        #pragma unroll
        for (int j = 0; j < 4; j++) acc2[i][j] = 0ULL;

    int arow = tid / 4;
    int acol = (tid % 4) * 4;
    int brow = tid / 32;
    int bcol = (tid % 32) * 4;

    for (int k0 = 0; k0 < K; k0 += 16) {
        #pragma unroll
        for (int r = 0; r < 2; r++) {
            int row = arow + r * 64;
            float4 a = *(const float4*)&A[(long)(bm + row) * K + k0 + acol];
            As[acol + 0][row] = a.x;
            As[acol + 1][row] = a.y;
            As[acol + 2][row] = a.z;
            As[acol + 3][row] = a.w;
        }
        #pragma unroll
        for (int r = 0; r < 2; r++) {
            int row = brow + r * 8;
            *(float4*)&Bs[row][bcol] =
                *(const float4*)&W[(long)(k0 + row) * N + bn + bcol];
        }
        __syncthreads();
        #pragma unroll
        for (int kk = 0; kk < 16; kk++) {
            float a[8];
            u64 b2[4];
            *(float4*)&a[0] = *(float4*)&As[kk][ty * 8];
            *(float4*)&a[4] = *(float4*)&As[kk][ty * 8 + 4];
            *(float4*)&b2[0] = *(float4*)&Bs[kk][tx * 8];
            *(float4*)&b2[2] = *(float4*)&Bs[kk][tx * 8 + 4];
            #pragma unroll
            for (int i = 0; i < 8; i++) {
                u64 a2 = pack2(a[i], a[i]);
                #pragma unroll
                for (int j = 0; j < 4; j++)
                    fma2(acc2[i][j], a2, b2[j]);
            }
        }
        __syncthreads();
    }

    #pragma unroll
    for (int i = 0; i < 8; i++) {
        long m = bm + ty * 8 + i;
        #pragma unroll
        for (int j = 0; j < 2; j++) {
            int n = bn + tx * 8 + j * 4;
            float4 av = *(float4*)&acc2[i][j * 2];
            float4 bi = *(const float4*)&bias[n];
            float4 o;
            o.x = av.x + bi.x;
            o.y = av.y + bi.y;
            o.z = av.z + bi.z;
            o.w = av.w + bi.w;
            if (RESID) {
                float4 r = *(const float4*)&resid[m * N + n];
                o.x += r.x; o.y += r.y; o.z += r.z; o.w += r.w;
            }
            *(float4*)&C[m * N + n] = o;
        }
    }
}

// ================= flash-style attention (f32x2 inner loops) =================
#define NCHK (SS / 64)   // 9
#define ATT_SMEM ((64*68 + 2*64*68 + 2*64*68 + 64*68 + SS) * 4)

__global__ __launch_bounds__(256)
void flash_attn_kernel(const float* __restrict__ mask) {
    extern __shared__ float sm[];
    float (*qs)[68]  = (float(*)[68])sm;          // [64][68]
    float (*ks)[68]  = qs + 64;                   // [2*64][68]
    float (*vs)[68]  = ks + 128;                  // [2*64][68]
    float (*pst)[68] = vs + 128;                  // [64][68] : pst[j][q]
    float* msm       = (float*)(pst + 64);        // [576]

    int idx = blockIdx.x;
    int qt = idx % NCHK;  idx /= NCHK;
    int h  = idx % NHEAD;
    int b  = idx / NHEAD;
    int q0 = qt * 64;

    int tid = threadIdx.x;
    int qg = tid >> 4;
    int jg = tid & 15;

    const float* qb = g_q + (long)b * SS * HH + h * HD;
    const float* kb = g_k + (long)b * SS * HH + h * HD;
    const float* vb = g_v + (long)b * SS * HH + h * HD;

    for (int i = tid; i < SS; i += 256) msm[i] = mask[b * SS + i];
    #pragma unroll
    for (int t = 0; t < 4; t++) {
        int e = tid + t * 256;
        int r = e >> 4, c = e & 15;
        *(float4*)&qs[r][c * 4] = *(const float4*)&qb[(long)(q0 + r) * HH + c * 4];
    }

    #pragma unroll
    for (int t = 0; t < 4; t++) {
        int e = tid + t * 256;
        int r = e >> 4, c = e & 15;
        cp_async16(smem_u32(&ks[r][c * 4]), kb + (long)r * HH + c * 4);
        cp_async16(smem_u32(&vs[r][c * 4]), vb + (long)r * HH + c * 4);
    }
    CP_COMMIT();

    float m[4], l[4];
    u64 acc2[4][2];
    #pragma unroll
    for (int i = 0; i < 4; i++) {
        m[i] = -1e30f; l[i] = 0.f;
        acc2[i][0] = 0ULL; acc2[i][1] = 0ULL;
    }

    for (int c = 0; c < NCHK; c++) {
        int buf = c & 1;
        if (c + 1 < NCHK) {
            int nb_ = buf ^ 1;
            long rbase = (long)(c + 1) * 64;
            #pragma unroll
            for (int t = 0; t < 4; t++) {
                int e = tid + t * 256;
                int r = e >> 4, cc = e & 15;
                cp_async16(smem_u32(&ks[nb_ * 64 + r][cc * 4]),
                           kb + (rbase + r) * HH + cc * 4);
                cp_async16(smem_u32(&vs[nb_ * 64 + r][cc * 4]),
                           vb + (rbase + r) * HH + cc * 4);
            }
            CP_COMMIT();
            CP_WAIT1();
        } else {
            CP_WAIT0();
        }
        __syncthreads();

        // ---- phase 2: scores via packed f32x2 along d ----
        u64 s2[4][4];
        #pragma unroll
        for (int i = 0; i < 4; i++)
            #pragma unroll
            for (int j = 0; j < 4; j++) s2[i][j] = 0ULL;

        #pragma unroll
        for (int d4 = 0; d4 < 16; d4++) {
            u64 q2[4][2];
            #pragma unroll
            for (int iq = 0; iq < 4; iq++)
                *(float4*)&q2[iq][0] = *(float4*)&qs[4 * qg + iq][d4 * 4];
            #pragma unroll
            for (int ij = 0; ij < 4; ij++) {
                u64 k2[2];
                *(float4*)&k2[0] = *(float4*)&ks[buf * 64 + jg + 16 * ij][d4 * 4];
                #pragma unroll
                for (int iq = 0; iq < 4; iq++) {
                    fma2(s2[iq][ij], q2[iq][0], k2[0]);
                    fma2(s2[iq][ij], q2[iq][1], k2[1]);
                }
            }
        }
        float s[4][4];
        #pragma unroll
        for (int iq = 0; iq < 4; iq++)
            #pragma unroll
            for (int ij = 0; ij < 4; ij++) {
                float2 f = *(float2*)&s2[iq][ij];
                s[iq][ij] = f.x + f.y;
            }

        // ---- phase 3/4: online softmax update ----
        float alpha[4];
        #pragma unroll
        for (int iq = 0; iq < 4; iq++) {
            float cm = -1e30f;
            #pragma unroll
            for (int ij = 0; ij < 4; ij++) {
                float v = s[iq][ij] * 0.125f + msm[c * 64 + jg + 16 * ij];
                s[iq][ij] = v;
                cm = fmaxf(cm, v);
            }
            #pragma unroll
            for (int o = 1; o < 16; o <<= 1)
                cm = fmaxf(cm, __shfl_xor_sync(0xffffffff, cm, o));
            float nm = fmaxf(m[iq], cm);
            alpha[iq] = fexp(m[iq] - nm);
            m[iq] = nm;
            float psum = 0.f;
            #pragma unroll
            for (int ij = 0; ij < 4; ij++) {
                float p = fexp(s[iq][ij] - nm);
                s[iq][ij] = p;
                psum += p;
            }
            #pragma unroll
            for (int o = 1; o < 16; o <<= 1)
                psum += __shfl_xor_sync(0xffffffff, psum, o);
            l[iq] = l[iq] * alpha[iq] + psum;
        }

        #pragma unroll
        for (int ij = 0; ij < 4; ij++) {
            float4 pv = make_float4(s[0][ij], s[1][ij], s[2][ij], s[3][ij]);
            *(float4*)&pst[jg + 16 * ij][4 * qg] = pv;
        }
        __syncthreads();

        // ---- phase 5: ctx accumulation with packed f32x2 ----
        #pragma unroll
        for (int iq = 0; iq < 4; iq++) {
            u64 al2 = pack2(alpha[iq], alpha[iq]);
            mul2(acc2[iq][0], al2);
            mul2(acc2[iq][1], al2);
        }
        #pragma unroll 4
        for (int j = 0; j < 64; j++) {
            float4 pv = *(float4*)&pst[j][4 * qg];
            u64 v2[2];
            *(float4*)&v2[0] = *(float4*)&vs[buf * 64 + j][jg * 4];
            u64 p0 = pack2(pv.x, pv.x);
            u64 p1 = pack2(pv.y, pv.y);
            u64 p2 = pack2(pv.z, pv.z);
            u64 p3 = pack2(pv.w, pv.w);
            fma2(acc2[0][0], p0, v2[0]); fma2(acc2[0][1], p0, v2[1]);
            fma2(acc2[1][0], p1, v2[0]); fma2(acc2[1][1], p1, v2[1]);
            fma2(acc2[2][0], p2, v2[0]); fma2(acc2[2][1], p2, v2[1]);
            fma2(acc2[3][0], p3, v2[0]); fma2(acc2[3][1], p3, v2[1]);
        }
        __syncthreads();
    }

    // ---- output ----
    #pragma unroll
    for (int iq = 0; iq < 4; iq++) {
        float inv = 1.0f / l[iq];
        float4 av = *(float4*)&acc2[iq][0];
        float4 o;
        o.x = av.x * inv; o.y = av.y * inv;
        o.z = av.z * inv; o.w = av.w * inv;
        long row = (long)b * SS + q0 + 4 * qg + iq;
        *(float4*)&g_ctx[row * HH + h * HD + jg * 4] = o;
    }
}

// ---------------- LayerNorm + output split ordering ----------------
__global__ __launch_bounds__(256)
void ln_out_kernel(const float* __restrict__ ln_w, const float* __restrict__ ln_b,
                   float* __restrict__ out) {
    int row = blockIdx.x;
    int b = row / SS, s = row % SS;
    const float* y = g_y + (long)row * HH;
    int tid = threadIdx.x;

    float4 v = *(const float4*)&y[tid * 4];
    float sum = v.x + v.y + v.z + v.w;
    float sq  = v.x * v.x + v.y * v.y + v.z * v.z + v.w * v.w;

    __shared__ float s_sum[8], s_sq[8], s_stats[2];
    int w = tid / 32, lane = tid % 32;
    #pragma unroll
    for (int o = 16; o > 0; o >>= 1) {
        sum += __shfl_xor_sync(0xffffffff, sum, o);
        sq  += __shfl_xor_sync(0xffffffff, sq,  o);
    }
    if (lane == 0) { s_sum[w] = sum; s_sq[w] = sq; }
    __syncthreads();
    if (tid == 0) {
        float ts = 0.f, tq = 0.f;
        #pragma unroll
        for (int i = 0; i < 8; i++) { ts += s_sum[i]; tq += s_sq[i]; }
        float mean = ts * (1.0f / HH);
        float var  = tq * (1.0f / HH) - mean * mean;
        s_stats[0] = mean;
        s_stats[1] = rsqrtf(var + 1e-12f);
    }
    __syncthreads();
    float mean = s_stats[0], inv = s_stats[1];

    long dst;
    if (s < LW) dst = ((long)b * LW + s) * HH;
    else        dst = (long)NB * LW * HH + ((long)b * LE + (s - LW)) * HH;

    float4 w4 = *(const float4*)&ln_w[tid * 4];
    float4 b4 = *(const float4*)&ln_b[tid * 4];
    float4 o;
    o.x = (v.x - mean) * inv * w4.x + b4.x;
    o.y = (v.y - mean) * inv * w4.y + b4.y;
    o.z = (v.z - mean) * inv * w4.z + b4.z;
    o.w = (v.w - mean) * inv * w4.w + b4.w;
    *(float4*)&out[dst + tid * 4] = o;
}

// ---------------- launch ----------------
extern "C" void kernel_launch(void* const* d_in, const int* in_sizes, int n_in,
                              void* d_out, int out_size) {
    const float* word = (const float*)d_in[0];
    const float* ent  = (const float*)d_in[1];
    const float* mask = (const float*)d_in[2];
    const float* Wq   = (const float*)d_in[3];
    const float* bq   = (const float*)d_in[4];
    const float* Wk   = (const float*)d_in[5];
    const float* bk   = (const float*)d_in[6];
    const float* Wv   = (const float*)d_in[7];
    const float* bv   = (const float*)d_in[8];
    const float* Wo   = (const float*)d_in[9];
    const float* bo   = (const float*)d_in[10];
    const float* lnw  = (const float*)d_in[11];
    const float* lnb  = (const float*)d_in[12];
    float* out = (float*)d_out;

    float *px, *pq, *pk, *pv, *pc, *py;
    cudaGetSymbolAddress((void**)&px, g_x);
    cudaGetSymbolAddress((void**)&pq, g_q);
    cudaGetSymbolAddress((void**)&pk, g_k);
    cudaGetSymbolAddress((void**)&pv, g_v);
    cudaGetSymbolAddress((void**)&pc, g_ctx);
    cudaGetSymbolAddress((void**)&py, g_y);

    cudaFuncSetAttribute(flash_attn_kernel,
                         cudaFuncAttributeMaxDynamicSharedMemorySize, ATT_SMEM);

    // 1) concat
    {
        long n4 = (long)MTOT * HH / 4;
        int blocks = (int)((n4 + 255) / 256);
        concat_kernel<<<blocks, 256>>>(word, ent);
    }

    // 2) Q/K/V projections
    {
        dim3 grid(HH / 128, MTOT / 128);
        gemm_kernel<false><<<grid, 256>>>(px, Wq, bq, nullptr, pq, MTOT, HH, HH);
        gemm_kernel<false><<<grid, 256>>>(px, Wk, bk, nullptr, pk, MTOT, HH, HH);
        gemm_kernel<false><<<grid, 256>>>(px, Wv, bv, nullptr, pv, MTOT, HH, HH);
    }

    // 3) flash attention
    flash_attn_kernel<<<NB * NHEAD * NCHK, 256, ATT_SMEM>>>(mask);

    // 4) output projection + bias + residual
    {
        dim3 grid(HH / 128, MTOT / 128);
        gemm_kernel<true><<<grid, 256>>>(pc, Wo, bo, px, py, MTOT, HH, HH);
    }

    // 5) LayerNorm + split write
    ln_out_kernel<<<MTOT, 256>>>(lnw, lnb, out);
}

// round 6
// speedup vs baseline: 1.5940x; 1.0247x over previous
#include <cuda_runtime.h>
#include <math.h>
#include <stdint.h>

#define NB 8
#define LW 512
#define LE 64
#define SS 576
#define HH 1024
#define NHEAD 16
#define HD 64
#define MTOT (NB*SS)      // 4608

typedef unsigned long long u64;

// ---------------- scratch (device globals; no allocation) ----------------
__device__ float g_x  [ (long)MTOT * HH ];
__device__ float g_q  [ (long)MTOT * HH ];
__device__ float g_k  [ (long)MTOT * HH ];
__device__ float g_v  [ (long)MTOT * HH ];
__device__ float g_ctx[ (long)MTOT * HH ];
__device__ float g_y  [ (long)MTOT * HH ];

// ---------------- packed f32x2 helpers (attention only) ----------------
__device__ __forceinline__ u64 pack2(float lo, float hi) {
    u64 r; asm("mov.b64 %0, {%1, %2};" : "=l"(r) : "f"(lo), "f"(hi)); return r;
}
__device__ __forceinline__ void fma2(u64& d, u64 a, u64 b) {
    asm("fma.rn.f32x2 %0, %1, %2, %0;" : "+l"(d) : "l"(a), "l"(b));
}
__device__ __forceinline__ void mul2(u64& d, u64 a) {
    asm("mul.rn.f32x2 %0, %0, %1;" : "+l"(d) : "l"(a));
}

// ---------------- fast exp on the FMA pipe (no MUFU) ----------------
__device__ __forceinline__ float fexp(float x) {
    float t = x * 1.4426950408889634f;
    t = fmaxf(t, -120.0f);
    int   e = __float2int_rn(t);
    float f = t - (float)e;
    const float c1 = 0.6931471805599453f;
    const float c2 = 0.2402265069591007f;
    const float c3 = 0.0555041086648216f;
    const float c4 = 0.0096181291076285f;
    const float c5 = 0.0013333558146428f;
    float p = fmaf(f, c5, c4);
    p = fmaf(f, p, c3);
    p = fmaf(f, p, c2);
    p = fmaf(f, p, c1);
    p = fmaf(f, p, 1.0f);
    float sc = __int_as_float((e + 127) << 23);
    return sc * p;
}

__device__ __forceinline__ uint32_t smem_u32(const void* p) {
    uint32_t a;
    asm("{ .reg .u64 t; cvta.to.shared.u64 t, %1; cvt.u32.u64 %0, t; }" : "=r"(a) : "l"(p));
    return a;
}
__device__ __forceinline__ void cp_async16(uint32_t dst, const void* src) {
    asm volatile("cp.async.cg.shared.global [%0], [%1], 16;" :: "r"(dst), "l"(src));
}
#define CP_COMMIT() asm volatile("cp.async.commit_group;" ::: "memory")
#define CP_WAIT1()  asm volatile("cp.async.wait_group 1;" ::: "memory")
#define CP_WAIT0()  asm volatile("cp.async.wait_group 0;" ::: "memory")

// ---------------- concat word/entity into g_x [B,S,H] ----------------
__global__ void concat_kernel(const float* __restrict__ w,
                              const float* __restrict__ e) {
    long i = (long)blockIdx.x * blockDim.x + threadIdx.x;
    long n4 = (long)MTOT * HH / 4;
    if (i >= n4) return;
    long idx = i * 4;
    int b = (int)(idx / ((long)SS * HH));
    long rem = idx % ((long)SS * HH);
    int s = (int)(rem / HH);
    int h = (int)(rem % HH);
    float4 val;
    if (s < LW) val = *(const float4*)&w[((long)b * LW + s) * HH + h];
    else        val = *(const float4*)&e[((long)b * LE + (s - LW)) * HH + h];
    *(float4*)&g_x[idx] = val;
}

// ------------- software-pipelined fp32 GEMM: C = A*W + bias (+resid) --------
// BM=BN=128, BK=16, 256 threads, 8x8 microtile, 2-stage buffers:
//   B staged by cp.async (direct copy), A via LDG->regs->STS(next buffer).
// ONE __syncthreads per k0.
template<bool RESID>
__global__ __launch_bounds__(256)
void gemm_kernel(const float* __restrict__ A, const float* __restrict__ W,
                 const float* __restrict__ bias, const float* __restrict__ resid,
                 float* __restrict__ C, int M, int N, int K) {
    __shared__ float As[2][16][132];
    __shared__ float Bs[2][16][128];

    int tid = threadIdx.x;
    int bm = blockIdx.y * 128;
    int bn = blockIdx.x * 128;
    int ty = tid / 16, tx = tid % 16;

    float acc[8][8];
    #pragma unroll
    for (int i = 0; i < 8; i++)
        #pragma unroll
        for (int j = 0; j < 8; j++) acc[i][j] = 0.f;

    int arow = tid / 4;            // 0..63 -> rows arow, arow+64
    int acol = (tid % 4) * 4;      // 0,4,8,12
    int brow = tid / 32;           // 0..7 -> rows brow, brow+8
    int bcol = (tid % 32) * 4;     // 0..124

    const float* Aptr0 = &A[(long)(bm + arow) * K + acol];
    const float* Aptr1 = &A[(long)(bm + arow + 64) * K + acol];
    const float* Wp0   = &W[(long)brow * N + bn + bcol];
    const float* Wp1   = &W[(long)(brow + 8) * N + bn + bcol];

    // ---- prologue: stage tile 0 ----
    {
        float4 a0 = *(const float4*)Aptr0;
        float4 a1 = *(const float4*)Aptr1;
        As[0][acol + 0][arow] = a0.x;
        As[0][acol + 1][arow] = a0.y;
        As[0][acol + 2][arow] = a0.z;
        As[0][acol + 3][arow] = a0.w;
        As[0][acol + 0][arow + 64] = a1.x;
        As[0][acol + 1][arow + 64] = a1.y;
        As[0][acol + 2][arow + 64] = a1.z;
        As[0][acol + 3][arow + 64] = a1.w;
        cp_async16(smem_u32(&Bs[0][brow][bcol]),     Wp0);
        cp_async16(smem_u32(&Bs[0][brow + 8][bcol]), Wp1);
        CP_COMMIT();
        CP_WAIT0();
        __syncthreads();
    }

    for (int k0 = 0; k0 < K; k0 += 16) {
        int cur = (k0 >> 4) & 1;
        int nxt = cur ^ 1;
        bool more = (k0 + 16 < K);

        float4 pa0, pa1;
        if (more) {
            // prefetch A(next) into regs; cp.async B(next)
            pa0 = *(const float4*)(Aptr0 + k0 + 16);
            pa1 = *(const float4*)(Aptr1 + k0 + 16);
            cp_async16(smem_u32(&Bs[nxt][brow][bcol]),
                       Wp0 + (long)(k0 + 16) * N);
            cp_async16(smem_u32(&Bs[nxt][brow + 8][bcol]),
                       Wp1 + (long)(k0 + 16) * N);
            CP_COMMIT();
        }

        #pragma unroll
        for (int kk = 0; kk < 16; kk++) {
            float a[8], b[8];
            *(float4*)&a[0] = *(float4*)&As[cur][kk][ty * 8];
            *(float4*)&a[4] = *(float4*)&As[cur][kk][ty * 8 + 4];
            *(float4*)&b[0] = *(float4*)&Bs[cur][kk][tx * 8];
            *(float4*)&b[4] = *(float4*)&Bs[cur][kk][tx * 8 + 4];
            #pragma unroll
            for (int i = 0; i < 8; i++)
                #pragma unroll
                for (int j = 0; j < 8; j++)
                    acc[i][j] = fmaf(a[i], b[j], acc[i][j]);
        }

        if (more) {
            As[nxt][acol + 0][arow] = pa0.x;
            As[nxt][acol + 1][arow] = pa0.y;
            As[nxt][acol + 2][arow] = pa0.z;
            As[nxt][acol + 3][arow] = pa0.w;
            As[nxt][acol + 0][arow + 64] = pa1.x;
            As[nxt][acol + 1][arow + 64] = pa1.y;
            As[nxt][acol + 2][arow + 64] = pa1.z;
            As[nxt][acol + 3][arow + 64] = pa1.w;
            CP_WAIT0();
            __syncthreads();
        }
    }

    #pragma unroll
    for (int i = 0; i < 8; i++) {
        long m = bm + ty * 8 + i;
        #pragma unroll
        for (int j = 0; j < 8; j += 4) {
            int n = bn + tx * 8 + j;
            float4 bi = *(const float4*)&bias[n];
            float4 o;
            o.x = acc[i][j + 0] + bi.x;
            o.y = acc[i][j + 1] + bi.y;
            o.z = acc[i][j + 2] + bi.z;
            o.w = acc[i][j + 3] + bi.w;
            if (RESID) {
                float4 r = *(const float4*)&resid[m * N + n];
                o.x += r.x; o.y += r.y; o.z += r.z; o.w += r.w;
            }
            *(float4*)&C[m * N + n] = o;
        }
    }
}

// ================= flash-style attention (unchanged from R5) =================
#define NCHK (SS / 64)   // 9
#define ATT_SMEM ((64*68 + 2*64*68 + 2*64*68 + 64*68 + SS) * 4)

__global__ __launch_bounds__(256)
void flash_attn_kernel(const float* __restrict__ mask) {
    extern __shared__ float sm[];
    float (*qs)[68]  = (float(*)[68])sm;
    float (*ks)[68]  = qs + 64;
    float (*vs)[68]  = ks + 128;
    float (*pst)[68] = vs + 128;
    float* msm       = (float*)(pst + 64);

    int idx = blockIdx.x;
    int qt = idx % NCHK;  idx /= NCHK;
    int h  = idx % NHEAD;
    int b  = idx / NHEAD;
    int q0 = qt * 64;

    int tid = threadIdx.x;
    int qg = tid >> 4;
    int jg = tid & 15;

    const float* qb = g_q + (long)b * SS * HH + h * HD;
    const float* kb = g_k + (long)b * SS * HH + h * HD;
    const float* vb = g_v + (long)b * SS * HH + h * HD;

    for (int i = tid; i < SS; i += 256) msm[i] = mask[b * SS + i];
    #pragma unroll
    for (int t = 0; t < 4; t++) {
        int e = tid + t * 256;
        int r = e >> 4, c = e & 15;
        *(float4*)&qs[r][c * 4] = *(const float4*)&qb[(long)(q0 + r) * HH + c * 4];
    }

    #pragma unroll
    for (int t = 0; t < 4; t++) {
        int e = tid + t * 256;
        int r = e >> 4, c = e & 15;
        cp_async16(smem_u32(&ks[r][c * 4]), kb + (long)r * HH + c * 4);
        cp_async16(smem_u32(&vs[r][c * 4]), vb + (long)r * HH + c * 4);
    }
    CP_COMMIT();

    float m[4], l[4];
    u64 acc2[4][2];
    #pragma unroll
    for (int i = 0; i < 4; i++) {
        m[i] = -1e30f; l[i] = 0.f;
        acc2[i][0] = 0ULL; acc2[i][1] = 0ULL;
    }

    for (int c = 0; c < NCHK; c++) {
        int buf = c & 1;
        if (c + 1 < NCHK) {
            int nb_ = buf ^ 1;
            long rbase = (long)(c + 1) * 64;
            #pragma unroll
            for (int t = 0; t < 4; t++) {
                int e = tid + t * 256;
                int r = e >> 4, cc = e & 15;
                cp_async16(smem_u32(&ks[nb_ * 64 + r][cc * 4]),
                           kb + (rbase + r) * HH + cc * 4);
                cp_async16(smem_u32(&vs[nb_ * 64 + r][cc * 4]),
                           vb + (rbase + r) * HH + cc * 4);
            }
            CP_COMMIT();
            CP_WAIT1();
        } else {
            CP_WAIT0();
        }
        __syncthreads();

        u64 s2[4][4];
        #pragma unroll
        for (int i = 0; i < 4; i++)
            #pragma unroll
            for (int j = 0; j < 4; j++) s2[i][j] = 0ULL;

        #pragma unroll
        for (int d4 = 0; d4 < 16; d4++) {
            u64 q2[4][2];
            #pragma unroll
            for (int iq = 0; iq < 4; iq++)
                *(float4*)&q2[iq][0] = *(float4*)&qs[4 * qg + iq][d4 * 4];
            #pragma unroll
            for (int ij = 0; ij < 4; ij++) {
                u64 k2[2];
                *(float4*)&k2[0] = *(float4*)&ks[buf * 64 + jg + 16 * ij][d4 * 4];
                #pragma unroll
                for (int iq = 0; iq < 4; iq++) {
                    fma2(s2[iq][ij], q2[iq][0], k2[0]);
                    fma2(s2[iq][ij], q2[iq][1], k2[1]);
                }
            }
        }
        float s[4][4];
        #pragma unroll
        for (int iq = 0; iq < 4; iq++)
            #pragma unroll
            for (int ij = 0; ij < 4; ij++) {
                float2 f = *(float2*)&s2[iq][ij];
                s[iq][ij] = f.x + f.y;
            }

        float alpha[4];
        #pragma unroll
        for (int iq = 0; iq < 4; iq++) {
            float cm = -1e30f;
            #pragma unroll
            for (int ij = 0; ij < 4; ij++) {
                float v = s[iq][ij] * 0.125f + msm[c * 64 + jg + 16 * ij];
                s[iq][ij] = v;
                cm = fmaxf(cm, v);
            }
            #pragma unroll
            for (int o = 1; o < 16; o <<= 1)
                cm = fmaxf(cm, __shfl_xor_sync(0xffffffff, cm, o));
            float nm = fmaxf(m[iq], cm);
            alpha[iq] = fexp(m[iq] - nm);
            m[iq] = nm;
            float psum = 0.f;
            #pragma unroll
            for (int ij = 0; ij < 4; ij++) {
                float p = fexp(s[iq][ij] - nm);
                s[iq][ij] = p;
                psum += p;
            }
            #pragma unroll
            for (int o = 1; o < 16; o <<= 1)
                psum += __shfl_xor_sync(0xffffffff, psum, o);
            l[iq] = l[iq] * alpha[iq] + psum;
        }

        #pragma unroll
        for (int ij = 0; ij < 4; ij++) {
            float4 pv = make_float4(s[0][ij], s[1][ij], s[2][ij], s[3][ij]);
            *(float4*)&pst[jg + 16 * ij][4 * qg] = pv;
        }
        __syncthreads();

        #pragma unroll
        for (int iq = 0; iq < 4; iq++) {
            u64 al2 = pack2(alpha[iq], alpha[iq]);
            mul2(acc2[iq][0], al2);
            mul2(acc2[iq][1], al2);
        }
        #pragma unroll 4
        for (int j = 0; j < 64; j++) {
            float4 pv = *(float4*)&pst[j][4 * qg];
            u64 v2[2];
            *(float4*)&v2[0] = *(float4*)&vs[buf * 64 + j][jg * 4];
            u64 p0 = pack2(pv.x, pv.x);
            u64 p1 = pack2(pv.y, pv.y);
            u64 p2 = pack2(pv.z, pv.z);
            u64 p3 = pack2(pv.w, pv.w);
            fma2(acc2[0][0], p0, v2[0]); fma2(acc2[0][1], p0, v2[1]);
            fma2(acc2[1][0], p1, v2[0]); fma2(acc2[1][1], p1, v2[1]);
            fma2(acc2[2][0], p2, v2[0]); fma2(acc2[2][1], p2, v2[1]);
            fma2(acc2[3][0], p3, v2[0]); fma2(acc2[3][1], p3, v2[1]);
        }
        __syncthreads();
    }

    #pragma unroll
    for (int iq = 0; iq < 4; iq++) {
        float inv = 1.0f / l[iq];
        float4 av = *(float4*)&acc2[iq][0];
        float4 o;
        o.x = av.x * inv; o.y = av.y * inv;
        o.z = av.z * inv; o.w = av.w * inv;
        long row = (long)b * SS + q0 + 4 * qg + iq;
        *(float4*)&g_ctx[row * HH + h * HD + jg * 4] = o;
    }
}

// ---------------- LayerNorm + output split ordering ----------------
__global__ __launch_bounds__(256)
void ln_out_kernel(const float* __restrict__ ln_w, const float* __restrict__ ln_b,
                   float* __restrict__ out) {
    int row = blockIdx.x;
    int b = row / SS, s = row % SS;
    const float* y = g_y + (long)row * HH;
    int tid = threadIdx.x;

    float4 v = *(const float4*)&y[tid * 4];
    float sum = v.x + v.y + v.z + v.w;
    float sq  = v.x * v.x + v.y * v.y + v.z * v.z + v.w * v.w;

    __shared__ float s_sum[8], s_sq[8], s_stats[2];
    int w = tid / 32, lane = tid % 32;
    #pragma unroll
    for (int o = 16; o > 0; o >>= 1) {
        sum += __shfl_xor_sync(0xffffffff, sum, o);
        sq  += __shfl_xor_sync(0xffffffff, sq,  o);
    }
    if (lane == 0) { s_sum[w] = sum; s_sq[w] = sq; }
    __syncthreads();
    if (tid == 0) {
        float ts = 0.f, tq = 0.f;
        #pragma unroll
        for (int i = 0; i < 8; i++) { ts += s_sum[i]; tq += s_sq[i]; }
        float mean = ts * (1.0f / HH);
        float var  = tq * (1.0f / HH) - mean * mean;
        s_stats[0] = mean;
        s_stats[1] = rsqrtf(var + 1e-12f);
    }
    __syncthreads();
    float mean = s_stats[0], inv = s_stats[1];

    long dst;
    if (s < LW) dst = ((long)b * LW + s) * HH;
    else        dst = (long)NB * LW * HH + ((long)b * LE + (s - LW)) * HH;

    float4 w4 = *(const float4*)&ln_w[tid * 4];
    float4 b4 = *(const float4*)&ln_b[tid * 4];
    float4 o;
    o.x = (v.x - mean) * inv * w4.x + b4.x;
    o.y = (v.y - mean) * inv * w4.y + b4.y;
    o.z = (v.z - mean) * inv * w4.z + b4.z;
    o.w = (v.w - mean) * inv * w4.w + b4.w;
    *(float4*)&out[dst + tid * 4] = o;
}

// ---------------- launch ----------------
extern "C" void kernel_launch(void* const* d_in, const int* in_sizes, int n_in,
                              void* d_out, int out_size) {
    const float* word = (const float*)d_in[0];
    const float* ent  = (const float*)d_in[1];
    const float* mask = (const float*)d_in[2];
    const float* Wq   = (const float*)d_in[3];
    const float* bq   = (const float*)d_in[4];
    const float* Wk   = (const float*)d_in[5];
    const float* bk   = (const float*)d_in[6];
    const float* Wv   = (const float*)d_in[7];
    const float* bv   = (const float*)d_in[8];
    const float* Wo   = (const float*)d_in[9];
    const float* bo   = (const float*)d_in[10];
    const float* lnw  = (const float*)d_in[11];
    const float* lnb  = (const float*)d_in[12];
    float* out = (float*)d_out;

    float *px, *pq, *pk, *pv, *pc, *py;
    cudaGetSymbolAddress((void**)&px, g_x);
    cudaGetSymbolAddress((void**)&pq, g_q);
    cudaGetSymbolAddress((void**)&pk, g_k);
    cudaGetSymbolAddress((void**)&pv, g_v);
    cudaGetSymbolAddress((void**)&pc, g_ctx);
    cudaGetSymbolAddress((void**)&py, g_y);

    cudaFuncSetAttribute(flash_attn_kernel,
                         cudaFuncAttributeMaxDynamicSharedMemorySize, ATT_SMEM);

    // 1) concat
    {
        long n4 = (long)MTOT * HH / 4;
        int blocks = (int)((n4 + 255) / 256);
        concat_kernel<<<blocks, 256>>>(word, ent);
    }

    // 2) Q/K/V projections
    {
        dim3 grid(HH / 128, MTOT / 128);
        gemm_kernel<false><<<grid, 256>>>(px, Wq, bq, nullptr, pq, MTOT, HH, HH);
        gemm_kernel<false><<<grid, 256>>>(px, Wk, bk, nullptr, pk, MTOT, HH, HH);
        gemm_kernel<false><<<grid, 256>>>(px, Wv, bv, nullptr, pv, MTOT, HH, HH);
    }

    // 3) flash attention
    flash_attn_kernel<<<NB * NHEAD * NCHK, 256, ATT_SMEM>>>(mask);

    // 4) output projection + bias + residual
    {
        dim3 grid(HH / 128, MTOT / 128);
        gemm_kernel<true><<<grid, 256>>>(pc, Wo, bo, px, py, MTOT, HH, HH);
    }

    // 5) LayerNorm + split write
    ln_out_kernel<<<MTOT, 256>>>(lnw, lnb, out);
}

// round 7
// speedup vs baseline: 1.6666x; 1.0455x over previous
#include <cuda_runtime.h>
#include <math.h>
#include <stdint.h>

#define NB 8
#define LW 512
#define LE 64
#define SS 576
#define HH 1024
#define NHEAD 16
#define HD 64
#define MTOT (NB*SS)      // 4608

typedef unsigned long long u64;

// ---------------- scratch (device globals; no allocation) ----------------
__device__ float g_q  [ (long)MTOT * HH ];
__device__ float g_k  [ (long)MTOT * HH ];
__device__ float g_v  [ (long)MTOT * HH ];
__device__ float g_ctx[ (long)MTOT * HH ];
__device__ float g_y  [ (long)MTOT * HH ];

// ---------------- packed f32x2 helpers (attention only) ----------------
__device__ __forceinline__ u64 pack2(float lo, float hi) {
    u64 r; asm("mov.b64 %0, {%1, %2};" : "=l"(r) : "f"(lo), "f"(hi)); return r;
}
__device__ __forceinline__ void fma2(u64& d, u64 a, u64 b) {
    asm("fma.rn.f32x2 %0, %1, %2, %0;" : "+l"(d) : "l"(a), "l"(b));
}
__device__ __forceinline__ void mul2(u64& d, u64 a) {
    asm("mul.rn.f32x2 %0, %0, %1;" : "+l"(d) : "l"(a));
}

// ---------------- fast exp on the FMA pipe (no MUFU) ----------------
__device__ __forceinline__ float fexp(float x) {
    float t = x * 1.4426950408889634f;
    t = fmaxf(t, -120.0f);
    int   e = __float2int_rn(t);
    float f = t - (float)e;
    const float c1 = 0.6931471805599453f;
    const float c2 = 0.2402265069591007f;
    const float c3 = 0.0555041086648216f;
    const float c4 = 0.0096181291076285f;
    const float c5 = 0.0013333558146428f;
    float p = fmaf(f, c5, c4);
    p = fmaf(f, p, c3);
    p = fmaf(f, p, c2);
    p = fmaf(f, p, c1);
    p = fmaf(f, p, 1.0f);
    float sc = __int_as_float((e + 127) << 23);
    return sc * p;
}

__device__ __forceinline__ uint32_t smem_u32(const void* p) {
    uint32_t a;
    asm("{ .reg .u64 t; cvta.to.shared.u64 t, %1; cvt.u32.u64 %0, t; }" : "=r"(a) : "l"(p));
    return a;
}
__device__ __forceinline__ void cp_async16(uint32_t dst, const void* src) {
    asm volatile("cp.async.cg.shared.global [%0], [%1], 16;" :: "r"(dst), "l"(src));
}
#define CP_COMMIT() asm volatile("cp.async.commit_group;" ::: "memory")
#define CP_WAIT1()  asm volatile("cp.async.wait_group 1;" ::: "memory")
#define CP_WAIT0()  asm volatile("cp.async.wait_group 0;" ::: "memory")

// row m of virtual concat([B,Lw,H] word, [B,Le,H] ent)
__device__ __forceinline__ const float* xrow(const float* __restrict__ word,
                                             const float* __restrict__ ent, int m) {
    int b = m / SS, s = m % SS;
    return (s < LW) ? word + ((long)b * LW + s) * HH
                    : ent  + ((long)b * LE + (s - LW)) * HH;
}

// ------------- software-pipelined fp32 GEMM, 16x8 microtile, 128 thr --------
// C[m,n] = sum_k A[m,k] * W[k,n] + bias[n] (+ resid[m,n])
// A is either a direct pointer or the virtual word/entity concat.
template<bool RESID, bool CONCAT_A>
__global__ __launch_bounds__(128)
void gemm_kernel(const float* __restrict__ Adirect,
                 const float* __restrict__ word,
                 const float* __restrict__ ent,
                 const float* __restrict__ W,
                 const float* __restrict__ bias,
                 float* __restrict__ C) {
    __shared__ float As[2][16][132];
    __shared__ float Bs[2][16][128];

    int tid = threadIdx.x;
    int bm = blockIdx.y * 128;
    int bn = blockIdx.x * 128;
    int ty = tid >> 4;          // 0..7  -> rows ty*16 .. +15
    int tx = tid & 15;          // 0..15 -> cols tx*8 .. +7

    float acc[16][8];
    #pragma unroll
    for (int i = 0; i < 16; i++)
        #pragma unroll
        for (int j = 0; j < 8; j++) acc[i][j] = 0.f;

    // A loader: thread handles 4 (row, 16B) pieces: rows tid/4 + 32t, col (tid&3)*4
    int arow_b = tid >> 2;          // 0..31
    int acol   = (tid & 3) * 4;     // 0,4,8,12
    const float* Aptr[4];
    #pragma unroll
    for (int t = 0; t < 4; t++) {
        int m = bm + arow_b + t * 32;
        Aptr[t] = (CONCAT_A ? xrow(word, ent, m)
                            : Adirect + (long)m * HH) + acol;
    }

    // B loader: 4 pieces: idx = tid + 128t; row idx>>5 (0..15), col16 = idx&31
    const float* Wp[4];
    uint32_t bdst[2][4];
    #pragma unroll
    for (int t = 0; t < 4; t++) {
        int idx = tid + t * 128;
        int br = idx >> 5, bc = (idx & 31) * 4;
        Wp[t] = W + (long)br * HH + bn + bc;
        bdst[0][t] = smem_u32(&Bs[0][br][bc]);
        bdst[1][t] = smem_u32(&Bs[1][br][bc]);
    }

    // ---- prologue: stage tile 0 ----
    {
        #pragma unroll
        for (int t = 0; t < 4; t++) {
            float4 a = *(const float4*)Aptr[t];
            int r = arow_b + t * 32;
            As[0][acol + 0][r] = a.x;
            As[0][acol + 1][r] = a.y;
            As[0][acol + 2][r] = a.z;
            As[0][acol + 3][r] = a.w;
            cp_async16(bdst[0][t], Wp[t]);
        }
        CP_COMMIT();
        CP_WAIT0();
        __syncthreads();
    }

    for (int k0 = 0; k0 < HH; k0 += 16) {
        int cur = (k0 >> 4) & 1;
        int nxt = cur ^ 1;
        bool more = (k0 + 16 < HH);

        float4 pa[4];
        if (more) {
            #pragma unroll
            for (int t = 0; t < 4; t++) {
                pa[t] = *(const float4*)(Aptr[t] + k0 + 16);
                cp_async16(bdst[nxt][t], Wp[t] + (long)(k0 + 16) * HH);
            }
            CP_COMMIT();
        }

        #pragma unroll
        for (int kk = 0; kk < 16; kk++) {
            float a[16], b[8];
            *(float4*)&a[0]  = *(float4*)&As[cur][kk][ty * 16];
            *(float4*)&a[4]  = *(float4*)&As[cur][kk][ty * 16 + 4];
            *(float4*)&a[8]  = *(float4*)&As[cur][kk][ty * 16 + 8];
            *(float4*)&a[12] = *(float4*)&As[cur][kk][ty * 16 + 12];
            *(float4*)&b[0]  = *(float4*)&Bs[cur][kk][tx * 8];
            *(float4*)&b[4]  = *(float4*)&Bs[cur][kk][tx * 8 + 4];
            #pragma unroll
            for (int i = 0; i < 16; i++)
                #pragma unroll
                for (int j = 0; j < 8; j++)
                    acc[i][j] = fmaf(a[i], b[j], acc[i][j]);
        }

        if (more) {
            #pragma unroll
            for (int t = 0; t < 4; t++) {
                int r = arow_b + t * 32;
                As[nxt][acol + 0][r] = pa[t].x;
                As[nxt][acol + 1][r] = pa[t].y;
                As[nxt][acol + 2][r] = pa[t].z;
                As[nxt][acol + 3][r] = pa[t].w;
            }
            CP_WAIT0();
            __syncthreads();
        }
    }

    // ---- epilogue ----
    #pragma unroll
    for (int i = 0; i < 16; i++) {
        int m = bm + ty * 16 + i;
        const float* rrow = RESID ? (xrow(word, ent, m) + bn) : nullptr;
        #pragma unroll
        for (int j = 0; j < 8; j += 4) {
            int n = bn + tx * 8 + j;
            float4 bi = *(const float4*)&bias[n];
            float4 o;
            o.x = acc[i][j + 0] + bi.x;
            o.y = acc[i][j + 1] + bi.y;
            o.z = acc[i][j + 2] + bi.z;
            o.w = acc[i][j + 3] + bi.w;
            if (RESID) {
                float4 r = *(const float4*)&rrow[tx * 8 + j];
                o.x += r.x; o.y += r.y; o.z += r.z; o.w += r.w;
            }
            *(float4*)&C[(long)m * HH + n] = o;
        }
    }
}

// ================= flash-style attention (unchanged) =================
#define NCHK (SS / 64)   // 9
#define ATT_SMEM ((64*68 + 2*64*68 + 2*64*68 + 64*68 + SS) * 4)

__global__ __launch_bounds__(256)
void flash_attn_kernel(const float* __restrict__ mask) {
    extern __shared__ float sm[];
    float (*qs)[68]  = (float(*)[68])sm;
    float (*ks)[68]  = qs + 64;
    float (*vs)[68]  = ks + 128;
    float (*pst)[68] = vs + 128;
    float* msm       = (float*)(pst + 64);

    int idx = blockIdx.x;
    int qt = idx % NCHK;  idx /= NCHK;
    int h  = idx % NHEAD;
    int b  = idx / NHEAD;
    int q0 = qt * 64;

    int tid = threadIdx.x;
    int qg = tid >> 4;
    int jg = tid & 15;

    const float* qb = g_q + (long)b * SS * HH + h * HD;
    const float* kb = g_k + (long)b * SS * HH + h * HD;
    const float* vb = g_v + (long)b * SS * HH + h * HD;

    for (int i = tid; i < SS; i += 256) msm[i] = mask[b * SS + i];
    #pragma unroll
    for (int t = 0; t < 4; t++) {
        int e = tid + t * 256;
        int r = e >> 4, c = e & 15;
        *(float4*)&qs[r][c * 4] = *(const float4*)&qb[(long)(q0 + r) * HH + c * 4];
    }

    #pragma unroll
    for (int t = 0; t < 4; t++) {
        int e = tid + t * 256;
        int r = e >> 4, c = e & 15;
        cp_async16(smem_u32(&ks[r][c * 4]), kb + (long)r * HH + c * 4);
        cp_async16(smem_u32(&vs[r][c * 4]), vb + (long)r * HH + c * 4);
    }
    CP_COMMIT();

    float m[4], l[4];
    u64 acc2[4][2];
    #pragma unroll
    for (int i = 0; i < 4; i++) {
        m[i] = -1e30f; l[i] = 0.f;
        acc2[i][0] = 0ULL; acc2[i][1] = 0ULL;
    }

    for (int c = 0; c < NCHK; c++) {
        int buf = c & 1;
        if (c + 1 < NCHK) {
            int nb_ = buf ^ 1;
            long rbase = (long)(c + 1) * 64;
            #pragma unroll
            for (int t = 0; t < 4; t++) {
                int e = tid + t * 256;
                int r = e >> 4, cc = e & 15;
                cp_async16(smem_u32(&ks[nb_ * 64 + r][cc * 4]),
                           kb + (rbase + r) * HH + cc * 4);
                cp_async16(smem_u32(&vs[nb_ * 64 + r][cc * 4]),
                           vb + (rbase + r) * HH + cc * 4);
            }
            CP_COMMIT();
            CP_WAIT1();
        } else {
            CP_WAIT0();
        }
        __syncthreads();

        u64 s2[4][4];
        #pragma unroll
        for (int i = 0; i < 4; i++)
            #pragma unroll
            for (int j = 0; j < 4; j++) s2[i][j] = 0ULL;

        #pragma unroll
        for (int d4 = 0; d4 < 16; d4++) {
            u64 q2[4][2];
            #pragma unroll
            for (int iq = 0; iq < 4; iq++)
                *(float4*)&q2[iq][0] = *(float4*)&qs[4 * qg + iq][d4 * 4];
            #pragma unroll
            for (int ij = 0; ij < 4; ij++) {
                u64 k2[2];
                *(float4*)&k2[0] = *(float4*)&ks[buf * 64 + jg + 16 * ij][d4 * 4];
                #pragma unroll
                for (int iq = 0; iq < 4; iq++) {
                    fma2(s2[iq][ij], q2[iq][0], k2[0]);
                    fma2(s2[iq][ij], q2[iq][1], k2[1]);
                }
            }
        }
        float s[4][4];
        #pragma unroll
        for (int iq = 0; iq < 4; iq++)
            #pragma unroll
            for (int ij = 0; ij < 4; ij++) {
                float2 f = *(float2*)&s2[iq][ij];
                s[iq][ij] = f.x + f.y;
            }

        float alpha[4];
        #pragma unroll
        for (int iq = 0; iq < 4; iq++) {
            float cm = -1e30f;
            #pragma unroll
            for (int ij = 0; ij < 4; ij++) {
                float v = s[iq][ij] * 0.125f + msm[c * 64 + jg + 16 * ij];
                s[iq][ij] = v;
                cm = fmaxf(cm, v);
            }
            #pragma unroll
            for (int o = 1; o < 16; o <<= 1)
                cm = fmaxf(cm, __shfl_xor_sync(0xffffffff, cm, o));
            float nm = fmaxf(m[iq], cm);
            alpha[iq] = fexp(m[iq] - nm);
            m[iq] = nm;
            float psum = 0.f;
            #pragma unroll
            for (int ij = 0; ij < 4; ij++) {
                float p = fexp(s[iq][ij] - nm);
                s[iq][ij] = p;
                psum += p;
            }
            #pragma unroll
            for (int o = 1; o < 16; o <<= 1)
                psum += __shfl_xor_sync(0xffffffff, psum, o);
            l[iq] = l[iq] * alpha[iq] + psum;
        }

        #pragma unroll
        for (int ij = 0; ij < 4; ij++) {
            float4 pv = make_float4(s[0][ij], s[1][ij], s[2][ij], s[3][ij]);
            *(float4*)&pst[jg + 16 * ij][4 * qg] = pv;
        }
        __syncthreads();

        #pragma unroll
        for (int iq = 0; iq < 4; iq++) {
            u64 al2 = pack2(alpha[iq], alpha[iq]);
            mul2(acc2[iq][0], al2);
            mul2(acc2[iq][1], al2);
        }
        #pragma unroll 4
        for (int j = 0; j < 64; j++) {
            float4 pv = *(float4*)&pst[j][4 * qg];
            u64 v2[2];
            *(float4*)&v2[0] = *(float4*)&vs[buf * 64 + j][jg * 4];
            u64 p0 = pack2(pv.x, pv.x);
            u64 p1 = pack2(pv.y, pv.y);
            u64 p2 = pack2(pv.z, pv.z);
            u64 p3 = pack2(pv.w, pv.w);
            fma2(acc2[0][0], p0, v2[0]); fma2(acc2[0][1], p0, v2[1]);
            fma2(acc2[1][0], p1, v2[0]); fma2(acc2[1][1], p1, v2[1]);
            fma2(acc2[2][0], p2, v2[0]); fma2(acc2[2][1], p2, v2[1]);
            fma2(acc2[3][0], p3, v2[0]); fma2(acc2[3][1], p3, v2[1]);
        }
        __syncthreads();
    }

    #pragma unroll
    for (int iq = 0; iq < 4; iq++) {
        float inv = 1.0f / l[iq];
        float4 av = *(float4*)&acc2[iq][0];
        float4 o;
        o.x = av.x * inv; o.y = av.y * inv;
        o.z = av.z * inv; o.w = av.w * inv;
        long row = (long)b * SS + q0 + 4 * qg + iq;
        *(float4*)&g_ctx[row * HH + h * HD + jg * 4] = o;
    }
}

// ---------------- LayerNorm + output split ordering ----------------
__global__ __launch_bounds__(256)
void ln_out_kernel(const float* __restrict__ ln_w, const float* __restrict__ ln_b,
                   float* __restrict__ out) {
    int row = blockIdx.x;
    int b = row / SS, s = row % SS;
    const float* y = g_y + (long)row * HH;
    int tid = threadIdx.x;

    float4 v = *(const float4*)&y[tid * 4];
    float sum = v.x + v.y + v.z + v.w;
    float sq  = v.x * v.x + v.y * v.y + v.z * v.z + v.w * v.w;

    __shared__ float s_sum[8], s_sq[8], s_stats[2];
    int w = tid / 32, lane = tid % 32;
    #pragma unroll
    for (int o = 16; o > 0; o >>= 1) {
        sum += __shfl_xor_sync(0xffffffff, sum, o);
        sq  += __shfl_xor_sync(0xffffffff, sq,  o);
    }
    if (lane == 0) { s_sum[w] = sum; s_sq[w] = sq; }
    __syncthreads();
    if (tid == 0) {
        float ts = 0.f, tq = 0.f;
        #pragma unroll
        for (int i = 0; i < 8; i++) { ts += s_sum[i]; tq += s_sq[i]; }
        float mean = ts * (1.0f / HH);
        float var  = tq * (1.0f / HH) - mean * mean;
        s_stats[0] = mean;
        s_stats[1] = rsqrtf(var + 1e-12f);
    }
    __syncthreads();
    float mean = s_stats[0], inv = s_stats[1];

    long dst;
    if (s < LW) dst = ((long)b * LW + s) * HH;
    else        dst = (long)NB * LW * HH + ((long)b * LE + (s - LW)) * HH;

    float4 w4 = *(const float4*)&ln_w[tid * 4];
    float4 b4 = *(const float4*)&ln_b[tid * 4];
    float4 o;
    o.x = (v.x - mean) * inv * w4.x + b4.x;
    o.y = (v.y - mean) * inv * w4.y + b4.y;
    o.z = (v.z - mean) * inv * w4.z + b4.z;
    o.w = (v.w - mean) * inv * w4.w + b4.w;
    *(float4*)&out[dst + tid * 4] = o;
}

// ---------------- launch ----------------
extern "C" void kernel_launch(void* const* d_in, const int* in_sizes, int n_in,
                              void* d_out, int out_size) {
    const float* word = (const float*)d_in[0];
    const float* ent  = (const float*)d_in[1];
    const float* mask = (const float*)d_in[2];
    const float* Wq   = (const float*)d_in[3];
    const float* bq   = (const float*)d_in[4];
    const float* Wk   = (const float*)d_in[5];
    const float* bk   = (const float*)d_in[6];
    const float* Wv   = (const float*)d_in[7];
    const float* bv   = (const float*)d_in[8];
    const float* Wo   = (const float*)d_in[9];
    const float* bo   = (const float*)d_in[10];
    const float* lnw  = (const float*)d_in[11];
    const float* lnb  = (const float*)d_in[12];
    float* out = (float*)d_out;

    float *pq, *pk, *pv, *pc, *py;
    cudaGetSymbolAddress((void**)&pq, g_q);
    cudaGetSymbolAddress((void**)&pk, g_k);
    cudaGetSymbolAddress((void**)&pv, g_v);
    cudaGetSymbolAddress((void**)&pc, g_ctx);
    cudaGetSymbolAddress((void**)&py, g_y);

    cudaFuncSetAttribute(flash_attn_kernel,
                         cudaFuncAttributeMaxDynamicSharedMemorySize, ATT_SMEM);

    dim3 grid(HH / 128, MTOT / 128);

    // 1) Q/K/V projections reading word/entity directly (virtual concat)
    gemm_kernel<false, true><<<grid, 128>>>(nullptr, word, ent, Wq, bq, pq);
    gemm_kernel<false, true><<<grid, 128>>>(nullptr, word, ent, Wk, bk, pk);
    gemm_kernel<false, true><<<grid, 128>>>(nullptr, word, ent, Wv, bv, pv);

    // 2) flash attention
    flash_attn_kernel<<<NB * NHEAD * NCHK, 256, ATT_SMEM>>>(mask);

    // 3) output projection + bias + residual (residual = virtual concat)
    gemm_kernel<true, false><<<grid, 128>>>(pc, word, ent, Wo, bo, py);

    // 4) LayerNorm + split write
    ln_out_kernel<<<MTOT, 256>>>(lnw, lnb, out);
}